// round 12
// baseline (speedup 1.0000x reference)
#include <cuda_runtime.h>
#include <cuda_fp16.h>
#include <cstdint>

#define E_DIM 4096
#define N_DIM 8192
#define FIN   256
#define HEADS 8
#define DOUT  64
#define HD    512
#define BATCH 2
#define LRELU_ALPHA 0.2f
#define NSLICE 16

// ---------------- scratch (fp16 operands, natural K-major layout) ----------------
__device__ __align__(16) __half g_x16[BATCH * N_DIM * FIN];
__device__ __align__(16) __half g_W16T[HD * FIN];
__device__ __align__(16) __half g_Hr16[N_DIM * E_DIM];       // (n, e)
__device__ __align__(16) __half g_HT16[E_DIM * N_DIM];       // (e, n)
__device__ __align__(16) __half g_Wh16[BATCH * N_DIM * HD];  // natural
__device__ __align__(16) __half g_WhT16[BATCH * HD * N_DIM]; // (hd, n)
__device__ __align__(16) __half g_m2T16[BATCH * HD * E_DIM]; // (hd, e), ae-scaled
__device__ float g_av[BATCH * N_DIM * HEADS];
__device__ float g_part[NSLICE * BATCH * E_DIM * HEADS];
__device__ float g_aeT[BATCH * HEADS * E_DIM];

__device__ __forceinline__ uint32_t smem_u32(const void* p) {
    uint32_t a;
    asm("{ .reg .u64 t; cvta.to.shared.u64 t, %1; cvt.u32.u64 %0, t; }" : "=r"(a) : "l"(p));
    return a;
}
__device__ __forceinline__ void cpa16(uint32_t dst, const void* src) {
    asm volatile("cp.async.cg.shared.global [%0], [%1], 16;" :: "r"(dst), "l"(src));
}
#define LDSM4(r0, r1, r2, r3, addr) \
    asm volatile("ldmatrix.sync.aligned.m8n8.x4.shared.b16 {%0,%1,%2,%3}, [%4];" \
        : "=r"(r0), "=r"(r1), "=r"(r2), "=r"(r3) : "r"(addr))

#define MMA_F16(c, a, b) \
    asm volatile("mma.sync.aligned.m16n8k16.row.col.f32.f16.f16.f32 " \
        "{%0,%1,%2,%3}, {%4,%5,%6,%7}, {%8,%9}, {%0,%1,%2,%3};" \
        : "+f"((c)[0]), "+f"((c)[1]), "+f"((c)[2]), "+f"((c)[3]) \
        : "r"((a)[0]), "r"((a)[1]), "r"((a)[2]), "r"((a)[3]), \
          "r"((b)[0]), "r"((b)[1]))

#define STG_BYTES 32768               // A 16KB + B 16KB (128 rows x 128B = 64 fp16)
#define STAGES 3
#define SMEM_SZ (STAGES * STG_BYTES)  // 96 KB

// ---------------- fp16 mma GEMM: CTA 128x128, 8 warps (32x64 each), K-step 64 ----------
// A: (M x K) fp16 K-major.  B: (N x K) fp16 K-major.  smem swizzle: group j ^ (row & 7).
// EPI 0: fp16 natural store + fused av (aeT = a_vertices)
// EPI 1: scale by aeT[bz,head(row),e(col)], fp16 natural store
// EPI 2: fp32 plain store
template<int EPI>
__global__ void __launch_bounds__(256, 2) hgemm(
    const __half* __restrict__ A, const __half* __restrict__ B, void* __restrict__ Cv,
    int K, int lda, int ldb, int ldc,
    long strideA, long strideB, long strideC, const float* __restrict__ aeT)
{
    extern __shared__ char smem[];
    const uint32_t sb = smem_u32(smem);
    const int tid = threadIdx.x, lane = tid & 31, wid = tid >> 5;
    const int wm = wid >> 1, wn = wid & 1;        // 4 x 2 warps, warp tile 32(M) x 64(N)
    const int m0 = blockIdx.y * 128, n0 = blockIdx.x * 128, bz = blockIdx.z;

    const __half* Ag = A + (long)bz * strideA + (long)m0 * lda;
    const __half* Bg = B + (long)bz * strideB + (long)n0 * ldb;

    auto load_stage = [&](int st, int k0) {
        const uint32_t sA = sb + st * STG_BYTES;
#pragma unroll
        for (int i = 0; i < 4; i++) {
            const int id = tid + i * 256;
            const int r = id >> 3, j = id & 7;
            cpa16(sA + r * 128 + ((j ^ (r & 7)) << 4), Ag + (long)r * lda + k0 + j * 8);
        }
        const uint32_t sB = sA + 16384;
#pragma unroll
        for (int i = 0; i < 4; i++) {
            const int id = tid + i * 256;
            const int r = id >> 3, j = id & 7;
            cpa16(sB + r * 128 + ((j ^ (r & 7)) << 4), Bg + (long)r * ldb + k0 + j * 8);
        }
    };

    float acc[2][8][4];
#pragma unroll
    for (int mt = 0; mt < 2; mt++)
#pragma unroll
        for (int nt = 0; nt < 8; nt++)
#pragma unroll
            for (int s = 0; s < 4; s++) acc[mt][nt][s] = 0.f;

    // ldmatrix per-lane geometry
    const int l7 = lane & 7, sub = lane >> 3;
    const int rowAl = (sub & 1) * 8 + l7;   // A x4: M rows 0-7,8-15 x k-halves
    const int kgA = sub >> 1;
    const int rowBl = (sub >> 1) * 8 + l7;  // B x4: n pairs x k-halves
    const int kgB = sub & 1;

    const int T = K / 64;
    load_stage(0, 0);
    asm volatile("cp.async.commit_group;" ::: "memory");
    load_stage(1, 64);
    asm volatile("cp.async.commit_group;" ::: "memory");

    for (int t = 0; t < T; t++) {
        asm volatile("cp.async.wait_group 1;" ::: "memory");
        __syncthreads();
        const int u = t + 2;
        if (u < T) load_stage(u % 3, u * 64);
        asm volatile("cp.async.commit_group;" ::: "memory");

        const uint32_t Ab = sb + (t % 3) * STG_BYTES;
        const uint32_t Bb = Ab + 16384;
        const uint32_t aRow = Ab + (wm * 32 + rowAl) * 128;
        const uint32_t bRow = Bb + (wn * 64 + rowBl) * 128;
#pragma unroll
        for (int kk = 0; kk < 4; kk++) {          // each kk = K=16
            const uint32_t gA = (uint32_t)((((kk << 1) | kgA) ^ l7) << 4);
            const uint32_t gB = (uint32_t)((((kk << 1) | kgB) ^ l7) << 4);
            uint32_t af[2][4], bf[8][2];
#pragma unroll
            for (int mt = 0; mt < 2; mt++)
                LDSM4(af[mt][0], af[mt][1], af[mt][2], af[mt][3],
                      aRow + mt * 16 * 128 + gA);
#pragma unroll
            for (int np = 0; np < 4; np++)
                LDSM4(bf[2 * np][0], bf[2 * np][1], bf[2 * np + 1][0], bf[2 * np + 1][1],
                      bRow + np * 16 * 128 + gB);
#pragma unroll
            for (int mt = 0; mt < 2; mt++)
#pragma unroll
                for (int nt = 0; nt < 8; nt++)
                    MMA_F16(acc[mt][nt], af[mt], bf[nt]);
        }
    }

    // ---------------- epilogue ----------------
    const int r4 = lane >> 2, cl = lane & 3;
    if (EPI == 0) {
        __half* Cb = (__half*)Cv;                 // flat (B*N) x HD
        const int head = (n0 >> 6) + wn;
        float aw0[8], aw1[8];
#pragma unroll
        for (int nt = 0; nt < 8; nt++) {
            aw0[nt] = aeT[nt * 8 + 2 * cl];
            aw1[nt] = aeT[nt * 8 + 2 * cl + 1];
        }
#pragma unroll
        for (int mt = 0; mt < 2; mt++) {
            const int row = m0 + wm * 32 + mt * 16 + r4;
            float s0 = 0.f, s1 = 0.f;
#pragma unroll
            for (int nt = 0; nt < 8; nt++) {
                const int col = n0 + wn * 64 + nt * 8 + 2 * cl;
                const __half h0 = __float2half_rn(acc[mt][nt][0]);
                const __half h1 = __float2half_rn(acc[mt][nt][1]);
                const __half h2 = __float2half_rn(acc[mt][nt][2]);
                const __half h3 = __float2half_rn(acc[mt][nt][3]);
                *(__half2*)&Cb[(long)row * ldc + col] = __halves2half2(h0, h1);
                *(__half2*)&Cb[(long)(row + 8) * ldc + col] = __halves2half2(h2, h3);
                s0 += __half2float(h0) * aw0[nt] + __half2float(h1) * aw1[nt];
                s1 += __half2float(h2) * aw0[nt] + __half2float(h3) * aw1[nt];
            }
            s0 += __shfl_xor_sync(0xffffffffu, s0, 1);
            s0 += __shfl_xor_sync(0xffffffffu, s0, 2);
            s1 += __shfl_xor_sync(0xffffffffu, s1, 1);
            s1 += __shfl_xor_sync(0xffffffffu, s1, 2);
            if (cl == 0) {
                g_av[(long)row * HEADS + head] =
                    fmaxf(s0, 0.f) + LRELU_ALPHA * fminf(s0, 0.f);
                g_av[(long)(row + 8) * HEADS + head] =
                    fmaxf(s1, 0.f) + LRELU_ALPHA * fminf(s1, 0.f);
            }
        }
    } else if (EPI == 1) {
        __half* Cb = (__half*)Cv + (long)bz * strideC;
        const int head = (m0 >> 6) + wm >> 1;     // not used; recompute below
        const int headR = (m0 >> 6) + (wm >> 1);  // 32-row strips: head = row/64
        (void)head;
        const float* aeb = aeT + ((long)bz * HEADS + headR) * E_DIM;
        float sc0[8], sc1[8];
#pragma unroll
        for (int nt = 0; nt < 8; nt++) {
            const int e = n0 + wn * 64 + nt * 8 + 2 * cl;
            sc0[nt] = aeb[e]; sc1[nt] = aeb[e + 1];
        }
#pragma unroll
        for (int mt = 0; mt < 2; mt++) {
            const int row = m0 + wm * 32 + mt * 16 + r4;
#pragma unroll
            for (int nt = 0; nt < 8; nt++) {
                const int col = n0 + wn * 64 + nt * 8 + 2 * cl;
                *(__half2*)&Cb[(long)row * ldc + col] = __halves2half2(
                    __float2half_rn(acc[mt][nt][0] * sc0[nt]),
                    __float2half_rn(acc[mt][nt][1] * sc1[nt]));
                *(__half2*)&Cb[(long)(row + 8) * ldc + col] = __halves2half2(
                    __float2half_rn(acc[mt][nt][2] * sc0[nt]),
                    __float2half_rn(acc[mt][nt][3] * sc1[nt]));
            }
        }
    } else {
        float* Cb = (float*)Cv + (long)bz * strideC;
#pragma unroll
        for (int mt = 0; mt < 2; mt++) {
            const int row = m0 + wm * 32 + mt * 16 + r4;
#pragma unroll
            for (int nt = 0; nt < 8; nt++) {
                const int col = n0 + wn * 64 + nt * 8 + 2 * cl;
                float2 o0 = {acc[mt][nt][0], acc[mt][nt][1]};
                float2 o1 = {acc[mt][nt][2], acc[mt][nt][3]};
                *(float2*)&Cb[(long)row * ldc + col] = o0;
                *(float2*)&Cb[(long)(row + 8) * ldc + col] = o1;
            }
        }
    }
}

// ---------------- prep kernels ----------------
__global__ __launch_bounds__(256) void prep_pack(const float* __restrict__ src,
                                                 __half* __restrict__ dst) {
    const long i = (long)blockIdx.x * 256 + threadIdx.x;
    float4 v0 = ((const float4*)src)[i * 2];
    float4 v1 = ((const float4*)src)[i * 2 + 1];
    __align__(16) __half h[8];
    h[0] = __float2half_rn(v0.x); h[1] = __float2half_rn(v0.y);
    h[2] = __float2half_rn(v0.z); h[3] = __float2half_rn(v0.w);
    h[4] = __float2half_rn(v1.x); h[5] = __float2half_rn(v1.y);
    h[6] = __float2half_rn(v1.z); h[7] = __float2half_rn(v1.w);
    ((uint4*)dst)[i] = *(const uint4*)h;
}
__global__ __launch_bounds__(256) void prep_WT(const float* __restrict__ W) {
    __shared__ float ts[32][33];
    const int o0 = blockIdx.x * 32, i0 = blockIdx.y * 32;
    const int tx = threadIdx.x & 31, ty = threadIdx.x >> 5;
#pragma unroll
    for (int r8 = 0; r8 < 4; r8++) {
        const int il = ty + r8 * 8;
        ts[tx][il] = W[(long)(i0 + il) * HD + o0 + tx];
    }
    __syncthreads();
#pragma unroll
    for (int r8 = 0; r8 < 4; r8++) {
        const int ol = ty + r8 * 8;
        g_W16T[(long)(o0 + ol) * FIN + i0 + tx] = __float2half_rn(ts[ol][tx]);
    }
}
__global__ __launch_bounds__(256) void prep_H(const float* __restrict__ H) {
    __shared__ __half ts[32][34];
    const int e0 = blockIdx.x * 32, n0 = blockIdx.y * 32;
    const int tx = threadIdx.x & 31, ty = threadIdx.x >> 5;
#pragma unroll
    for (int r8 = 0; r8 < 4; r8++) {
        const int nl = ty + r8 * 8;
        const __half h = __float2half_rn(H[(long)(n0 + nl) * E_DIM + e0 + tx]);
        g_Hr16[(long)(n0 + nl) * E_DIM + e0 + tx] = h;
        ts[tx][nl] = h;
    }
    __syncthreads();
#pragma unroll
    for (int r8 = 0; r8 < 4; r8++) {
        const int el = ty + r8 * 8;
        g_HT16[(long)(e0 + el) * N_DIM + n0 + tx] = ts[el][tx];
    }
}
__global__ __launch_bounds__(256) void trWh() {
    __shared__ __half ts[32][34];
    const int h0 = blockIdx.x * 32;
    const int n0g = blockIdx.y * 32;
    const int b = n0g >> 13, nn0 = n0g & (N_DIM - 1);
    const int tx = threadIdx.x & 31, ty = threadIdx.x >> 5;
#pragma unroll
    for (int r8 = 0; r8 < 4; r8++) {
        const int nl = ty + r8 * 8;
        ts[tx][nl] = g_Wh16[(long)(n0g + nl) * HD + h0 + tx];
    }
    __syncthreads();
#pragma unroll
    for (int r8 = 0; r8 < 4; r8++) {
        const int hl = ty + r8 * 8;
        g_WhT16[((long)b * HD + h0 + hl) * N_DIM + nn0 + tx] = ts[hl][tx];
    }
}

// ---------------- logits / softmax (exact fp32) ----------------
__global__ __launch_bounds__(256) void logits_kernel(const float* __restrict__ H) {
    const int e = blockIdx.x * 256 + threadIdx.x;
    const int slice = blockIdx.y;
    const int nbeg = slice * (N_DIM / NSLICE);
    float acc[16];
#pragma unroll
    for (int j = 0; j < 16; j++) acc[j] = 0.f;
    __shared__ float avs[64][16];
    for (int nc = 0; nc < N_DIM / NSLICE; nc += 64) {
        __syncthreads();
        for (int i = threadIdx.x; i < 64 * 16; i += 256) {
            const int nn = i >> 4, bh = i & 15;
            avs[nn][bh] = g_av[((long)(bh >> 3) * N_DIM + nbeg + nc + nn) * HEADS + (bh & 7)];
        }
        __syncthreads();
        for (int nn = 0; nn < 64; nn++) {
            const float hv = H[(long)(nbeg + nc + nn) * E_DIM + e];
#pragma unroll
            for (int j = 0; j < 16; j++) acc[j] += hv * avs[nn][j];
        }
    }
#pragma unroll
    for (int j = 0; j < 16; j++)
        g_part[(((long)slice * BATCH + (j >> 3)) * E_DIM + e) * HEADS + (j & 7)] = acc[j];
}

__global__ __launch_bounds__(1024) void softmax_kernel() {
    const int bb = blockIdx.x >> 3, hh = blockIdx.x & 7;
    const int t = threadIdx.x;
    float v[E_DIM / 1024];
    float mx = -1e30f;
#pragma unroll
    for (int i = 0; i < E_DIM / 1024; i++) {
        const int e = i * 1024 + t;
        float s = 0.f;
        for (int sl = 0; sl < NSLICE; sl++)
            s += g_part[(((long)sl * BATCH + bb) * E_DIM + e) * HEADS + hh];
        v[i] = s; mx = fmaxf(mx, s);
    }
    __shared__ float red[1024];
    red[t] = mx; __syncthreads();
    for (int o = 512; o; o >>= 1) { if (t < o) red[t] = fmaxf(red[t], red[t + o]); __syncthreads(); }
    mx = red[0]; __syncthreads();
    float sum = 0.f;
#pragma unroll
    for (int i = 0; i < E_DIM / 1024; i++) { v[i] = __expf(v[i] - mx); sum += v[i]; }
    red[t] = sum; __syncthreads();
    for (int o = 512; o; o >>= 1) { if (t < o) red[t] += red[t + o]; __syncthreads(); }
    const float inv = 1.f / red[0];
#pragma unroll
    for (int i = 0; i < E_DIM / 1024; i++)
        g_aeT[((long)bb * HEADS + hh) * E_DIM + i * 1024 + t] = v[i] * inv;
}

// ---------------- launch ----------------
extern "C" void kernel_launch(void* const* d_in, const int* in_sizes, int n_in,
                              void* d_out, int out_size)
{
    const float* x = (const float*)d_in[0];
    const float* H = (const float*)d_in[1];
    const float* W = (const float*)d_in[2];
    const float* a = (const float*)d_in[3];
    float* out = (float*)d_out;

    __half *px16, *pW16T, *pHr16, *pHT16, *pWh16, *pWhT16, *pm2T16;
    float *paeT;
    cudaGetSymbolAddress((void**)&px16, g_x16);
    cudaGetSymbolAddress((void**)&pW16T, g_W16T);
    cudaGetSymbolAddress((void**)&pHr16, g_Hr16);
    cudaGetSymbolAddress((void**)&pHT16, g_HT16);
    cudaGetSymbolAddress((void**)&pWh16, g_Wh16);
    cudaGetSymbolAddress((void**)&pWhT16, g_WhT16);
    cudaGetSymbolAddress((void**)&pm2T16, g_m2T16);
    cudaGetSymbolAddress((void**)&paeT, g_aeT);

    cudaFuncSetAttribute(hgemm<0>, cudaFuncAttributeMaxDynamicSharedMemorySize, SMEM_SZ);
    cudaFuncSetAttribute(hgemm<1>, cudaFuncAttributeMaxDynamicSharedMemorySize, SMEM_SZ);
    cudaFuncSetAttribute(hgemm<2>, cudaFuncAttributeMaxDynamicSharedMemorySize, SMEM_SZ);

    // prep
    prep_pack<<<BATCH * N_DIM * FIN / 8 / 256, 256>>>(x, px16);
    prep_WT<<<dim3(HD / 32, FIN / 32), 256>>>(W);
    prep_H<<<dim3(E_DIM / 32, N_DIM / 32), 256>>>(H);

    // 1) Wh = x @ W (+ fused av) : M=16384, N=512, K=256
    hgemm<0><<<dim3(HD / 128, (BATCH * N_DIM) / 128, 1), 256, SMEM_SZ>>>(
        px16, pW16T, pWh16, FIN, FIN, FIN, HD, 0, 0, 0, a);
    // logits + softmax
    logits_kernel<<<dim3(E_DIM / 256, NSLICE), 256>>>(H);
    softmax_kernel<<<BATCH * HEADS, 1024>>>();
    // transpose Wh
    trWh<<<dim3(HD / 32, BATCH * N_DIM / 32), 256>>>();
    // 5) m2T[b] = ae ⊙ (WhT[b] @ HT^T) : M=HD, N=E, K=N_DIM
    hgemm<1><<<dim3(E_DIM / 128, HD / 128, BATCH), 256, SMEM_SZ>>>(
        pWhT16, pHT16, pm2T16, N_DIM, N_DIM, N_DIM, E_DIM,
        (long)HD * N_DIM, 0, (long)HD * E_DIM, paeT);
    // 6) out[b] = Hr @ m2T[b]^T : M=N_DIM, N=HD, K=E
    hgemm<2><<<dim3(HD / 128, N_DIM / 128, BATCH), 256, SMEM_SZ>>>(
        pHr16, pm2T16, out, E_DIM, E_DIM, E_DIM, HD,
        0, (long)HD * E_DIM, (long)N_DIM * HD, nullptr);
}

// round 13
// speedup vs baseline: 1.0909x; 1.0909x over previous
#include <cuda_runtime.h>
#include <cuda_fp16.h>
#include <cstdint>

#define E_DIM 4096
#define N_DIM 8192
#define FIN   256
#define HEADS 8
#define DOUT  64
#define HD    512
#define BATCH 2
#define LRELU_ALPHA 0.2f
#define NSLICE 16

// ---------------- scratch (fp16 operands, natural K-major layout) ----------------
__device__ __align__(16) __half g_x16[BATCH * N_DIM * FIN];
__device__ __align__(16) __half g_W16T[HD * FIN];
__device__ __align__(16) __half g_Hr16[N_DIM * E_DIM];       // (n, e)
__device__ __align__(16) __half g_HT16[E_DIM * N_DIM];       // (e, n)
__device__ __align__(16) __half g_Wh16[BATCH * N_DIM * HD];  // natural
__device__ __align__(16) __half g_WhT16[BATCH * HD * N_DIM]; // (hd, n)
__device__ __align__(16) __half g_m2T16[BATCH * HD * E_DIM]; // (hd, e), ae-scaled
__device__ float g_av[BATCH * N_DIM * HEADS];
__device__ float g_part[NSLICE * BATCH * E_DIM * HEADS];
__device__ float g_aeT[BATCH * HEADS * E_DIM];

__device__ __forceinline__ uint32_t smem_u32(const void* p) {
    uint32_t a;
    asm("{ .reg .u64 t; cvta.to.shared.u64 t, %1; cvt.u32.u64 %0, t; }" : "=r"(a) : "l"(p));
    return a;
}
__device__ __forceinline__ void cpa16(uint32_t dst, const void* src) {
    asm volatile("cp.async.cg.shared.global [%0], [%1], 16;" :: "r"(dst), "l"(src));
}
#define LDSM4(r0, r1, r2, r3, addr) \
    asm volatile("ldmatrix.sync.aligned.m8n8.x4.shared.b16 {%0,%1,%2,%3}, [%4];" \
        : "=r"(r0), "=r"(r1), "=r"(r2), "=r"(r3) : "r"(addr))

#define MMA_F16(c, a, b) \
    asm volatile("mma.sync.aligned.m16n8k16.row.col.f32.f16.f16.f32 " \
        "{%0,%1,%2,%3}, {%4,%5,%6,%7}, {%8,%9}, {%0,%1,%2,%3};" \
        : "+f"((c)[0]), "+f"((c)[1]), "+f"((c)[2]), "+f"((c)[3]) \
        : "r"((a)[0]), "r"((a)[1]), "r"((a)[2]), "r"((a)[3]), \
          "r"((b)[0]), "r"((b)[1]))

#define STG_BYTES 32768               // A 16KB + B 16KB (128 rows x 128B = 64 fp16)
#define STAGES 3
#define SMEM_SZ (STAGES * STG_BYTES)  // 96 KB

// ---------------- fp16 mma GEMM: CTA 128x128, 4 warps (64x64), K-step 64 ----------------
// A: (M x K) fp16 K-major.  B: (N x K) fp16 K-major.  smem swizzle: group j ^ (row & 7).
// EPI 0: fp16 natural store + fused av (aeT = a_vertices)
// EPI 1: scale by aeT[head(row), e(col)] (aeT pre-offset per batch), fp16 natural store
// EPI 2: fp32 plain store
template<int EPI>
__global__ void __launch_bounds__(128, 2) hgemm(
    const __half* __restrict__ A, const __half* __restrict__ B, void* __restrict__ Cv,
    int K, int lda, int ldb, int ldc, const float* __restrict__ aeT)
{
    extern __shared__ char smem[];
    const uint32_t sb = smem_u32(smem);
    const int tid = threadIdx.x, lane = tid & 31, wid = tid >> 5;
    const int wm = wid >> 1, wn = wid & 1;
    const int m0 = blockIdx.y * 128, n0 = blockIdx.x * 128;

    const __half* Ag = A + (long)m0 * lda;
    const __half* Bg = B + (long)n0 * ldb;

    auto load_stage = [&](int st, int k0) {
        const uint32_t sA = sb + st * STG_BYTES;
#pragma unroll
        for (int i = 0; i < 8; i++) {
            const int id = tid + i * 128;
            const int r = id >> 3, j = id & 7;
            cpa16(sA + r * 128 + ((j ^ (r & 7)) << 4), Ag + (long)r * lda + k0 + j * 8);
        }
        const uint32_t sB = sA + 16384;
#pragma unroll
        for (int i = 0; i < 8; i++) {
            const int id = tid + i * 128;
            const int r = id >> 3, j = id & 7;
            cpa16(sB + r * 128 + ((j ^ (r & 7)) << 4), Bg + (long)r * ldb + k0 + j * 8);
        }
    };

    float acc[4][8][4];
#pragma unroll
    for (int mt = 0; mt < 4; mt++)
#pragma unroll
        for (int nt = 0; nt < 8; nt++)
#pragma unroll
            for (int s = 0; s < 4; s++) acc[mt][nt][s] = 0.f;

    // ldmatrix per-lane geometry
    const int l7 = lane & 7, sub = lane >> 3;
    const int rowAl = (sub & 1) * 8 + l7;
    const int kgA = sub >> 1;
    const int rowBl = (sub >> 1) * 8 + l7;
    const int kgB = sub & 1;

    const int T = K / 64;
    load_stage(0, 0);
    asm volatile("cp.async.commit_group;" ::: "memory");
    load_stage(1, 64);
    asm volatile("cp.async.commit_group;" ::: "memory");

    for (int t = 0; t < T; t++) {
        asm volatile("cp.async.wait_group 1;" ::: "memory");
        __syncthreads();
        const int u = t + 2;
        if (u < T) load_stage(u % 3, u * 64);
        asm volatile("cp.async.commit_group;" ::: "memory");

        const uint32_t Ab = sb + (t % 3) * STG_BYTES;
        const uint32_t Bb = Ab + 16384;
        const uint32_t aRow = Ab + (wm * 64 + rowAl) * 128;
        const uint32_t bRow = Bb + (wn * 64 + rowBl) * 128;
#pragma unroll
        for (int kk = 0; kk < 4; kk++) {          // each kk = K=16
            const uint32_t gA = (uint32_t)((((kk << 1) | kgA) ^ l7) << 4);
            const uint32_t gB = (uint32_t)((((kk << 1) | kgB) ^ l7) << 4);
            uint32_t af[4][4], bf[8][2];
#pragma unroll
            for (int mt = 0; mt < 4; mt++)
                LDSM4(af[mt][0], af[mt][1], af[mt][2], af[mt][3],
                      aRow + mt * 16 * 128 + gA);
#pragma unroll
            for (int np = 0; np < 4; np++)
                LDSM4(bf[2 * np][0], bf[2 * np][1], bf[2 * np + 1][0], bf[2 * np + 1][1],
                      bRow + np * 16 * 128 + gB);
#pragma unroll
            for (int mt = 0; mt < 4; mt++)
#pragma unroll
                for (int nt = 0; nt < 8; nt++)
                    MMA_F16(acc[mt][nt], af[mt], bf[nt]);
        }
    }

    // ---------------- epilogue ----------------
    const int r4 = lane >> 2, cl = lane & 3;
    if (EPI == 0) {
        __half* Cb = (__half*)Cv;                 // flat (B*N) x HD
        const int head = (n0 >> 6) + wn;
        float aw0[8], aw1[8];
#pragma unroll
        for (int nt = 0; nt < 8; nt++) {
            aw0[nt] = aeT[nt * 8 + 2 * cl];
            aw1[nt] = aeT[nt * 8 + 2 * cl + 1];
        }
#pragma unroll
        for (int mt = 0; mt < 4; mt++) {
            const int row = m0 + wm * 64 + mt * 16 + r4;
            float s0 = 0.f, s1 = 0.f;
#pragma unroll
            for (int nt = 0; nt < 8; nt++) {
                const int col = n0 + wn * 64 + nt * 8 + 2 * cl;
                const __half h0 = __float2half_rn(acc[mt][nt][0]);
                const __half h1 = __float2half_rn(acc[mt][nt][1]);
                const __half h2 = __float2half_rn(acc[mt][nt][2]);
                const __half h3 = __float2half_rn(acc[mt][nt][3]);
                *(__half2*)&Cb[(long)row * ldc + col] = __halves2half2(h0, h1);
                *(__half2*)&Cb[(long)(row + 8) * ldc + col] = __halves2half2(h2, h3);
                s0 += __half2float(h0) * aw0[nt] + __half2float(h1) * aw1[nt];
                s1 += __half2float(h2) * aw0[nt] + __half2float(h3) * aw1[nt];
            }
            s0 += __shfl_xor_sync(0xffffffffu, s0, 1);
            s0 += __shfl_xor_sync(0xffffffffu, s0, 2);
            s1 += __shfl_xor_sync(0xffffffffu, s1, 1);
            s1 += __shfl_xor_sync(0xffffffffu, s1, 2);
            if (cl == 0) {
                g_av[(long)row * HEADS + head] =
                    fmaxf(s0, 0.f) + LRELU_ALPHA * fminf(s0, 0.f);
                g_av[(long)(row + 8) * HEADS + head] =
                    fmaxf(s1, 0.f) + LRELU_ALPHA * fminf(s1, 0.f);
            }
        }
    } else if (EPI == 1) {
        __half* Cb = (__half*)Cv;
        const int head = (m0 >> 6) + wm;
        const float* aeb = aeT + (long)head * E_DIM;
        float sc0[8], sc1[8];
#pragma unroll
        for (int nt = 0; nt < 8; nt++) {
            const int e = n0 + wn * 64 + nt * 8 + 2 * cl;
            sc0[nt] = aeb[e]; sc1[nt] = aeb[e + 1];
        }
#pragma unroll
        for (int mt = 0; mt < 4; mt++) {
            const int row = m0 + wm * 64 + mt * 16 + r4;
#pragma unroll
            for (int nt = 0; nt < 8; nt++) {
                const int col = n0 + wn * 64 + nt * 8 + 2 * cl;
                *(__half2*)&Cb[(long)row * ldc + col] = __halves2half2(
                    __float2half_rn(acc[mt][nt][0] * sc0[nt]),
                    __float2half_rn(acc[mt][nt][1] * sc1[nt]));
                *(__half2*)&Cb[(long)(row + 8) * ldc + col] = __halves2half2(
                    __float2half_rn(acc[mt][nt][2] * sc0[nt]),
                    __float2half_rn(acc[mt][nt][3] * sc1[nt]));
            }
        }
    } else {
        float* Cb = (float*)Cv;
#pragma unroll
        for (int mt = 0; mt < 4; mt++) {
            const int row = m0 + wm * 64 + mt * 16 + r4;
#pragma unroll
            for (int nt = 0; nt < 8; nt++) {
                const int col = n0 + wn * 64 + nt * 8 + 2 * cl;
                float2 o0 = {acc[mt][nt][0], acc[mt][nt][1]};
                float2 o1 = {acc[mt][nt][2], acc[mt][nt][3]};
                *(float2*)&Cb[(long)row * ldc + col] = o0;
                *(float2*)&Cb[(long)(row + 8) * ldc + col] = o1;
            }
        }
    }
}

// ---------------- prep kernels ----------------
__global__ __launch_bounds__(256) void prep_pack(const float* __restrict__ src,
                                                 __half* __restrict__ dst) {
    const long i = (long)blockIdx.x * 256 + threadIdx.x;
    float4 v0 = ((const float4*)src)[i * 2];
    float4 v1 = ((const float4*)src)[i * 2 + 1];
    __align__(16) __half h[8];
    h[0] = __float2half_rn(v0.x); h[1] = __float2half_rn(v0.y);
    h[2] = __float2half_rn(v0.z); h[3] = __float2half_rn(v0.w);
    h[4] = __float2half_rn(v1.x); h[5] = __float2half_rn(v1.y);
    h[6] = __float2half_rn(v1.z); h[7] = __float2half_rn(v1.w);
    ((uint4*)dst)[i] = *(const uint4*)h;
}
__global__ __launch_bounds__(256) void prep_WT(const float* __restrict__ W) {
    __shared__ float ts[32][33];
    const int o0 = blockIdx.x * 32, i0 = blockIdx.y * 32;
    const int tx = threadIdx.x & 31, ty = threadIdx.x >> 5;
#pragma unroll
    for (int r8 = 0; r8 < 4; r8++) {
        const int il = ty + r8 * 8;
        ts[tx][il] = W[(long)(i0 + il) * HD + o0 + tx];
    }
    __syncthreads();
#pragma unroll
    for (int r8 = 0; r8 < 4; r8++) {
        const int ol = ty + r8 * 8;
        g_W16T[(long)(o0 + ol) * FIN + i0 + tx] = __float2half_rn(ts[ol][tx]);
    }
}
__global__ __launch_bounds__(256) void prep_H(const float* __restrict__ H) {
    __shared__ __half ts[32][34];
    const int e0 = blockIdx.x * 32, n0 = blockIdx.y * 32;
    const int tx = threadIdx.x & 31, ty = threadIdx.x >> 5;
#pragma unroll
    for (int r8 = 0; r8 < 4; r8++) {
        const int nl = ty + r8 * 8;
        const __half h = __float2half_rn(H[(long)(n0 + nl) * E_DIM + e0 + tx]);
        g_Hr16[(long)(n0 + nl) * E_DIM + e0 + tx] = h;
        ts[tx][nl] = h;
    }
    __syncthreads();
#pragma unroll
    for (int r8 = 0; r8 < 4; r8++) {
        const int el = ty + r8 * 8;
        g_HT16[(long)(e0 + el) * N_DIM + n0 + tx] = ts[el][tx];
    }
}
__global__ __launch_bounds__(256) void trWh() {
    __shared__ __half ts[32][34];
    const int h0 = blockIdx.x * 32;
    const int n0g = blockIdx.y * 32;
    const int b = n0g >> 13, nn0 = n0g & (N_DIM - 1);
    const int tx = threadIdx.x & 31, ty = threadIdx.x >> 5;
#pragma unroll
    for (int r8 = 0; r8 < 4; r8++) {
        const int nl = ty + r8 * 8;
        ts[tx][nl] = g_Wh16[(long)(n0g + nl) * HD + h0 + tx];
    }
    __syncthreads();
#pragma unroll
    for (int r8 = 0; r8 < 4; r8++) {
        const int hl = ty + r8 * 8;
        g_WhT16[((long)b * HD + h0 + hl) * N_DIM + nn0 + tx] = ts[hl][tx];
    }
}

// ---------------- logits / softmax (exact fp32) ----------------
__global__ __launch_bounds__(256) void logits_kernel(const float* __restrict__ H) {
    const int e = blockIdx.x * 256 + threadIdx.x;
    const int slice = blockIdx.y;
    const int nbeg = slice * (N_DIM / NSLICE);
    float acc[16];
#pragma unroll
    for (int j = 0; j < 16; j++) acc[j] = 0.f;
    __shared__ float avs[64][16];
    for (int nc = 0; nc < N_DIM / NSLICE; nc += 64) {
        __syncthreads();
        for (int i = threadIdx.x; i < 64 * 16; i += 256) {
            const int nn = i >> 4, bh = i & 15;
            avs[nn][bh] = g_av[((long)(bh >> 3) * N_DIM + nbeg + nc + nn) * HEADS + (bh & 7)];
        }
        __syncthreads();
        for (int nn = 0; nn < 64; nn++) {
            const float hv = H[(long)(nbeg + nc + nn) * E_DIM + e];
#pragma unroll
            for (int j = 0; j < 16; j++) acc[j] += hv * avs[nn][j];
        }
    }
#pragma unroll
    for (int j = 0; j < 16; j++)
        g_part[(((long)slice * BATCH + (j >> 3)) * E_DIM + e) * HEADS + (j & 7)] = acc[j];
}

__global__ __launch_bounds__(1024) void softmax_kernel() {
    const int bb = blockIdx.x >> 3, hh = blockIdx.x & 7;
    const int t = threadIdx.x;
    float v[E_DIM / 1024];
    float mx = -1e30f;
#pragma unroll
    for (int i = 0; i < E_DIM / 1024; i++) {
        const int e = i * 1024 + t;
        float s = 0.f;
        for (int sl = 0; sl < NSLICE; sl++)
            s += g_part[(((long)sl * BATCH + bb) * E_DIM + e) * HEADS + hh];
        v[i] = s; mx = fmaxf(mx, s);
    }
    __shared__ float red[1024];
    red[t] = mx; __syncthreads();
    for (int o = 512; o; o >>= 1) { if (t < o) red[t] = fmaxf(red[t], red[t + o]); __syncthreads(); }
    mx = red[0]; __syncthreads();
    float sum = 0.f;
#pragma unroll
    for (int i = 0; i < E_DIM / 1024; i++) { v[i] = __expf(v[i] - mx); sum += v[i]; }
    red[t] = sum; __syncthreads();
    for (int o = 512; o; o >>= 1) { if (t < o) red[t] += red[t + o]; __syncthreads(); }
    const float inv = 1.f / red[0];
#pragma unroll
    for (int i = 0; i < E_DIM / 1024; i++)
        g_aeT[((long)bb * HEADS + hh) * E_DIM + i * 1024 + t] = v[i] * inv;
}

// ---------------- launch (stream fork-join inside graph capture) ----------------
extern "C" void kernel_launch(void* const* d_in, const int* in_sizes, int n_in,
                              void* d_out, int out_size)
{
    const float* x = (const float*)d_in[0];
    const float* H = (const float*)d_in[1];
    const float* W = (const float*)d_in[2];
    const float* a = (const float*)d_in[3];
    float* out = (float*)d_out;

    __half *px16, *pW16T, *pHr16, *pHT16, *pWh16, *pWhT16, *pm2T16;
    float *paeT;
    cudaGetSymbolAddress((void**)&px16, g_x16);
    cudaGetSymbolAddress((void**)&pW16T, g_W16T);
    cudaGetSymbolAddress((void**)&pHr16, g_Hr16);
    cudaGetSymbolAddress((void**)&pHT16, g_HT16);
    cudaGetSymbolAddress((void**)&pWh16, g_Wh16);
    cudaGetSymbolAddress((void**)&pWhT16, g_WhT16);
    cudaGetSymbolAddress((void**)&pm2T16, g_m2T16);
    cudaGetSymbolAddress((void**)&paeT, g_aeT);

    cudaFuncSetAttribute(hgemm<0>, cudaFuncAttributeMaxDynamicSharedMemorySize, SMEM_SZ);
    cudaFuncSetAttribute(hgemm<1>, cudaFuncAttributeMaxDynamicSharedMemorySize, SMEM_SZ);
    cudaFuncSetAttribute(hgemm<2>, cudaFuncAttributeMaxDynamicSharedMemorySize, SMEM_SZ);

    // side stream + events (created per call, intentionally not destroyed:
    // destroying capture-participating resources mid-capture is UB; leak is
    // bounded — kernel_launch runs only for correctness + capture)
    cudaStream_t s2;
    cudaStreamCreate(&s2);
    cudaEvent_t evFork, evPrep, evG0, evSM, evJoin;
    cudaEventCreateWithFlags(&evFork, cudaEventDisableTiming);
    cudaEventCreateWithFlags(&evPrep, cudaEventDisableTiming);
    cudaEventCreateWithFlags(&evG0, cudaEventDisableTiming);
    cudaEventCreateWithFlags(&evSM, cudaEventDisableTiming);
    cudaEventCreateWithFlags(&evJoin, cudaEventDisableTiming);

    // fork s2 from origin (default) stream
    cudaEventRecord(evFork, 0);
    cudaStreamWaitEvent(s2, evFork, 0);

    // s2: prep_H (independent, DRAM-heavy)
    prep_H<<<dim3(E_DIM / 32, N_DIM / 32), 256, 0, s2>>>(H);

    // s0: pack x, transpose W, GEMM1 (+fused av)
    prep_pack<<<BATCH * N_DIM * FIN / 8 / 256, 256>>>(x, px16);
    prep_WT<<<dim3(HD / 32, FIN / 32), 256>>>(W);
    hgemm<0><<<dim3(HD / 128, (BATCH * N_DIM) / 128, 1), 128, SMEM_SZ>>>(
        px16, pW16T, pWh16, FIN, FIN, FIN, HD, a);
    cudaEventRecord(evG0, 0);

    // s2: trWh after GEMM1 (overlaps logits on s0)
    cudaStreamWaitEvent(s2, evG0, 0);
    trWh<<<dim3(HD / 32, BATCH * N_DIM / 32), 256, 0, s2>>>();
    cudaEventRecord(evPrep, s2);      // prep_H + trWh both done on s2

    // s0: logits + softmax
    logits_kernel<<<dim3(E_DIM / 256, NSLICE), 256>>>(H);
    softmax_kernel<<<BATCH * HEADS, 1024>>>();
    cudaEventRecord(evSM, 0);

    // batch chains: b0 on s0, b1 on s2 (each: GEMM5 -> GEMM6)
    cudaStreamWaitEvent(0, evPrep, 0);
    cudaStreamWaitEvent(s2, evSM, 0);

    // b0 on s0
    hgemm<1><<<dim3(E_DIM / 128, HD / 128, 1), 128, SMEM_SZ>>>(
        pWhT16, pHT16, pm2T16, N_DIM, N_DIM, N_DIM, E_DIM, paeT);
    hgemm<2><<<dim3(HD / 128, N_DIM / 128, 1), 128, SMEM_SZ>>>(
        pHr16, pm2T16, out, E_DIM, E_DIM, E_DIM, HD, nullptr);
    // b1 on s2
    hgemm<1><<<dim3(E_DIM / 128, HD / 128, 1), 128, SMEM_SZ, s2>>>(
        pWhT16 + (long)HD * N_DIM, pHT16, pm2T16 + (long)HD * E_DIM,
        N_DIM, N_DIM, N_DIM, E_DIM, paeT + (long)HEADS * E_DIM);
    hgemm<2><<<dim3(HD / 128, N_DIM / 128, 1), 128, SMEM_SZ, s2>>>(
        pHr16, pm2T16 + (long)HD * E_DIM, out + (long)N_DIM * HD,
        E_DIM, E_DIM, E_DIM, HD, nullptr);

    // join s2 back into origin stream
    cudaEventRecord(evJoin, s2);
    cudaStreamWaitEvent(0, evJoin, 0);
}

// round 16
// speedup vs baseline: 1.0987x; 1.0071x over previous
#include <cuda_runtime.h>
#include <cuda_fp16.h>
#include <cstdint>

#define E_DIM 4096
#define N_DIM 8192
#define FIN   256
#define HEADS 8
#define DOUT  64
#define HD    512
#define BATCH 2
#define LRELU_ALPHA 0.2f
#define NSLICE 16

// ---------------- scratch (fp16 operands, natural K-major layout) ----------------
__device__ __align__(16) __half g_x16[BATCH * N_DIM * FIN];
__device__ __align__(16) __half g_W16T[HD * FIN];
__device__ __align__(16) __half g_Hr16[N_DIM * E_DIM];       // (n, e)
__device__ __align__(16) __half g_HT16[E_DIM * N_DIM];       // (e, n)
__device__ __align__(16) __half g_Wh16[BATCH * N_DIM * HD];  // natural
__device__ __align__(16) __half g_WhT16[BATCH * HD * N_DIM]; // (hd, n)
__device__ __align__(16) __half g_m2T16[BATCH * HD * E_DIM]; // (hd, e); unscaled then ae-scaled
__device__ float g_av[BATCH * N_DIM * HEADS];
__device__ float g_part[NSLICE * BATCH * E_DIM * HEADS];
__device__ float g_aeT[BATCH * HEADS * E_DIM];

__device__ __forceinline__ uint32_t smem_u32(const void* p) {
    uint32_t a;
    asm("{ .reg .u64 t; cvta.to.shared.u64 t, %1; cvt.u32.u64 %0, t; }" : "=r"(a) : "l"(p));
    return a;
}
__device__ __forceinline__ void cpa16(uint32_t dst, const void* src) {
    asm volatile("cp.async.cg.shared.global [%0], [%1], 16;" :: "r"(dst), "l"(src));
}
#define LDSM4(r0, r1, r2, r3, addr) \
    asm volatile("ldmatrix.sync.aligned.m8n8.x4.shared.b16 {%0,%1,%2,%3}, [%4];" \
        : "=r"(r0), "=r"(r1), "=r"(r2), "=r"(r3) : "r"(addr))

#define MMA_F16(c, a, b) \
    asm volatile("mma.sync.aligned.m16n8k16.row.col.f32.f16.f16.f32 " \
        "{%0,%1,%2,%3}, {%4,%5,%6,%7}, {%8,%9}, {%0,%1,%2,%3};" \
        : "+f"((c)[0]), "+f"((c)[1]), "+f"((c)[2]), "+f"((c)[3]) \
        : "r"((a)[0]), "r"((a)[1]), "r"((a)[2]), "r"((a)[3]), \
          "r"((b)[0]), "r"((b)[1]))

#define STG_BYTES 32768               // A 16KB + B 16KB (128 rows x 128B = 64 fp16)
#define STAGES 3
#define SMEM_SZ (STAGES * STG_BYTES)  // 96 KB

// ---------------- fp16 mma GEMM: CTA 128x128, 4 warps (64x64), K-step 64 ----------------
// A: (M x K) fp16 K-major.  B: (N x K) fp16 K-major.  smem swizzle: group j ^ (row & 7).
// EPI 0: fp16 natural store + fused av (aeT = a_vertices)
// EPI 2: fp32 plain store
// EPI 3: fp16 plain store (unscaled)
template<int EPI>
__global__ void __launch_bounds__(128, 2) hgemm(
    const __half* __restrict__ A, const __half* __restrict__ B, void* __restrict__ Cv,
    int K, int lda, int ldb, int ldc, const float* __restrict__ aeT)
{
    extern __shared__ char smem[];
    const uint32_t sb = smem_u32(smem);
    const int tid = threadIdx.x, lane = tid & 31, wid = tid >> 5;
    const int wm = wid >> 1, wn = wid & 1;
    const int m0 = blockIdx.y * 128, n0 = blockIdx.x * 128;

    const __half* Ag = A + (long)m0 * lda;
    const __half* Bg = B + (long)n0 * ldb;

    auto load_stage = [&](int st, int k0) {
        const uint32_t sA = sb + st * STG_BYTES;
#pragma unroll
        for (int i = 0; i < 8; i++) {
            const int id = tid + i * 128;
            const int r = id >> 3, j = id & 7;
            cpa16(sA + r * 128 + ((j ^ (r & 7)) << 4), Ag + (long)r * lda + k0 + j * 8);
        }
        const uint32_t sB = sA + 16384;
#pragma unroll
        for (int i = 0; i < 8; i++) {
            const int id = tid + i * 128;
            const int r = id >> 3, j = id & 7;
            cpa16(sB + r * 128 + ((j ^ (r & 7)) << 4), Bg + (long)r * ldb + k0 + j * 8);
        }
    };

    float acc[4][8][4];
#pragma unroll
    for (int mt = 0; mt < 4; mt++)
#pragma unroll
        for (int nt = 0; nt < 8; nt++)
#pragma unroll
            for (int s = 0; s < 4; s++) acc[mt][nt][s] = 0.f;

    // ldmatrix per-lane geometry
    const int l7 = lane & 7, sub = lane >> 3;
    const int rowAl = (sub & 1) * 8 + l7;
    const int kgA = sub >> 1;
    const int rowBl = (sub >> 1) * 8 + l7;
    const int kgB = sub & 1;

    const int T = K / 64;
    load_stage(0, 0);
    asm volatile("cp.async.commit_group;" ::: "memory");
    load_stage(1, 64);
    asm volatile("cp.async.commit_group;" ::: "memory");

    for (int t = 0; t < T; t++) {
        asm volatile("cp.async.wait_group 1;" ::: "memory");
        __syncthreads();
        const int u = t + 2;
        if (u < T) load_stage(u % 3, u * 64);
        asm volatile("cp.async.commit_group;" ::: "memory");

        const uint32_t Ab = sb + (t % 3) * STG_BYTES;
        const uint32_t Bb = Ab + 16384;
        const uint32_t aRow = Ab + (wm * 64 + rowAl) * 128;
        const uint32_t bRow = Bb + (wn * 64 + rowBl) * 128;
#pragma unroll
        for (int kk = 0; kk < 4; kk++) {          // each kk = K=16
            const uint32_t gA = (uint32_t)((((kk << 1) | kgA) ^ l7) << 4);
            const uint32_t gB = (uint32_t)((((kk << 1) | kgB) ^ l7) << 4);
            uint32_t af[4][4], bf[8][2];
#pragma unroll
            for (int mt = 0; mt < 4; mt++)
                LDSM4(af[mt][0], af[mt][1], af[mt][2], af[mt][3],
                      aRow + mt * 16 * 128 + gA);
#pragma unroll
            for (int np = 0; np < 4; np++)
                LDSM4(bf[2 * np][0], bf[2 * np][1], bf[2 * np + 1][0], bf[2 * np + 1][1],
                      bRow + np * 16 * 128 + gB);
#pragma unroll
            for (int mt = 0; mt < 4; mt++)
#pragma unroll
                for (int nt = 0; nt < 8; nt++)
                    MMA_F16(acc[mt][nt], af[mt], bf[nt]);
        }
    }

    // ---------------- epilogue ----------------
    const int r4 = lane >> 2, cl = lane & 3;
    if (EPI == 0) {
        __half* Cb = (__half*)Cv;                 // flat (B*N) x HD
        const int head = (n0 >> 6) + wn;
        float aw0[8], aw1[8];
#pragma unroll
        for (int nt = 0; nt < 8; nt++) {
            aw0[nt] = aeT[nt * 8 + 2 * cl];
            aw1[nt] = aeT[nt * 8 + 2 * cl + 1];
        }
#pragma unroll
        for (int mt = 0; mt < 4; mt++) {
            const int row = m0 + wm * 64 + mt * 16 + r4;
            float s0 = 0.f, s1 = 0.f;
#pragma unroll
            for (int nt = 0; nt < 8; nt++) {
                const int col = n0 + wn * 64 + nt * 8 + 2 * cl;
                const __half h0 = __float2half_rn(acc[mt][nt][0]);
                const __half h1 = __float2half_rn(acc[mt][nt][1]);
                const __half h2 = __float2half_rn(acc[mt][nt][2]);
                const __half h3 = __float2half_rn(acc[mt][nt][3]);
                *(__half2*)&Cb[(long)row * ldc + col] = __halves2half2(h0, h1);
                *(__half2*)&Cb[(long)(row + 8) * ldc + col] = __halves2half2(h2, h3);
                s0 += __half2float(h0) * aw0[nt] + __half2float(h1) * aw1[nt];
                s1 += __half2float(h2) * aw0[nt] + __half2float(h3) * aw1[nt];
            }
            s0 += __shfl_xor_sync(0xffffffffu, s0, 1);
            s0 += __shfl_xor_sync(0xffffffffu, s0, 2);
            s1 += __shfl_xor_sync(0xffffffffu, s1, 1);
            s1 += __shfl_xor_sync(0xffffffffu, s1, 2);
            if (cl == 0) {
                g_av[(long)row * HEADS + head] =
                    fmaxf(s0, 0.f) + LRELU_ALPHA * fminf(s0, 0.f);
                g_av[(long)(row + 8) * HEADS + head] =
                    fmaxf(s1, 0.f) + LRELU_ALPHA * fminf(s1, 0.f);
            }
        }
    } else if (EPI == 3) {
        __half* Cb = (__half*)Cv;
#pragma unroll
        for (int mt = 0; mt < 4; mt++) {
            const int row = m0 + wm * 64 + mt * 16 + r4;
#pragma unroll
            for (int nt = 0; nt < 8; nt++) {
                const int col = n0 + wn * 64 + nt * 8 + 2 * cl;
                *(__half2*)&Cb[(long)row * ldc + col] = __halves2half2(
                    __float2half_rn(acc[mt][nt][0]), __float2half_rn(acc[mt][nt][1]));
                *(__half2*)&Cb[(long)(row + 8) * ldc + col] = __halves2half2(
                    __float2half_rn(acc[mt][nt][2]), __float2half_rn(acc[mt][nt][3]));
            }
        }
    } else {
        float* Cb = (float*)Cv;
#pragma unroll
        for (int mt = 0; mt < 4; mt++) {
            const int row = m0 + wm * 64 + mt * 16 + r4;
#pragma unroll
            for (int nt = 0; nt < 8; nt++) {
                const int col = n0 + wn * 64 + nt * 8 + 2 * cl;
                float2 o0 = {acc[mt][nt][0], acc[mt][nt][1]};
                float2 o1 = {acc[mt][nt][2], acc[mt][nt][3]};
                *(float2*)&Cb[(long)row * ldc + col] = o0;
                *(float2*)&Cb[(long)(row + 8) * ldc + col] = o1;
            }
        }
    }
}

// ---------------- ae scaling pass: m2T[hd, e] *= aeT[hd/64, e]  (per batch) ----------
// FIXED: one uint4 = 8 halfs per thread (R15 treated it as 16 -> half the buffer
// was never scaled + stack overrun).
__global__ __launch_bounds__(256) void scale_m2(__half* __restrict__ m2T,
                                                const float* __restrict__ aeT) {
    const int idx = blockIdx.x * 256 + threadIdx.x;        // uint4 id = 8 halfs
    const int perRow = E_DIM / 8;                          // 512 uint4 per hd row
    const int hd = idx / perRow, e0 = (idx % perRow) * 8;
    const float* ae = aeT + (long)(hd >> 6) * E_DIM + e0;
    uint4 v = ((uint4*)m2T)[idx];
    __half2* h2 = (__half2*)&v;
#pragma unroll
    for (int i = 0; i < 4; i++) {
        float2 f = __half22float2(h2[i]);
        f.x *= ae[2 * i]; f.y *= ae[2 * i + 1];
        h2[i] = __float22half2_rn(f);
    }
    ((uint4*)m2T)[idx] = v;
}

// ---------------- prep kernels ----------------
__global__ __launch_bounds__(256) void prep_pack(const float* __restrict__ src,
                                                 __half* __restrict__ dst) {
    const long i = (long)blockIdx.x * 256 + threadIdx.x;
    float4 v0 = ((const float4*)src)[i * 2];
    float4 v1 = ((const float4*)src)[i * 2 + 1];
    __align__(16) __half h[8];
    h[0] = __float2half_rn(v0.x); h[1] = __float2half_rn(v0.y);
    h[2] = __float2half_rn(v0.z); h[3] = __float2half_rn(v0.w);
    h[4] = __float2half_rn(v1.x); h[5] = __float2half_rn(v1.y);
    h[6] = __float2half_rn(v1.z); h[7] = __float2half_rn(v1.w);
    ((uint4*)dst)[i] = *(const uint4*)h;
}
__global__ __launch_bounds__(256) void prep_WT(const float* __restrict__ W) {
    __shared__ float ts[32][33];
    const int o0 = blockIdx.x * 32, i0 = blockIdx.y * 32;
    const int tx = threadIdx.x & 31, ty = threadIdx.x >> 5;
#pragma unroll
    for (int r8 = 0; r8 < 4; r8++) {
        const int il = ty + r8 * 8;
        ts[tx][il] = W[(long)(i0 + il) * HD + o0 + tx];
    }
    __syncthreads();
#pragma unroll
    for (int r8 = 0; r8 < 4; r8++) {
        const int ol = ty + r8 * 8;
        g_W16T[(long)(o0 + ol) * FIN + i0 + tx] = __float2half_rn(ts[ol][tx]);
    }
}
__global__ __launch_bounds__(256) void prep_H(const float* __restrict__ H) {
    __shared__ __half ts[32][34];
    const int e0 = blockIdx.x * 32, n0 = blockIdx.y * 32;
    const int tx = threadIdx.x & 31, ty = threadIdx.x >> 5;
#pragma unroll
    for (int r8 = 0; r8 < 4; r8++) {
        const int nl = ty + r8 * 8;
        const __half h = __float2half_rn(H[(long)(n0 + nl) * E_DIM + e0 + tx]);
        g_Hr16[(long)(n0 + nl) * E_DIM + e0 + tx] = h;
        ts[tx][nl] = h;
    }
    __syncthreads();
#pragma unroll
    for (int r8 = 0; r8 < 4; r8++) {
        const int el = ty + r8 * 8;
        g_HT16[(long)(e0 + el) * N_DIM + n0 + tx] = ts[el][tx];
    }
}
__global__ __launch_bounds__(256) void trWh() {
    __shared__ __half ts[32][34];
    const int h0 = blockIdx.x * 32;
    const int n0g = blockIdx.y * 32;
    const int b = n0g >> 13, nn0 = n0g & (N_DIM - 1);
    const int tx = threadIdx.x & 31, ty = threadIdx.x >> 5;
#pragma unroll
    for (int r8 = 0; r8 < 4; r8++) {
        const int nl = ty + r8 * 8;
        ts[tx][nl] = g_Wh16[(long)(n0g + nl) * HD + h0 + tx];
    }
    __syncthreads();
#pragma unroll
    for (int r8 = 0; r8 < 4; r8++) {
        const int hl = ty + r8 * 8;
        g_WhT16[((long)b * HD + h0 + hl) * N_DIM + nn0 + tx] = ts[hl][tx];
    }
}

// ---------------- logits / softmax (exact fp32) ----------------
__global__ __launch_bounds__(256) void logits_kernel(const float* __restrict__ H) {
    const int e = blockIdx.x * 256 + threadIdx.x;
    const int slice = blockIdx.y;
    const int nbeg = slice * (N_DIM / NSLICE);
    float acc[16];
#pragma unroll
    for (int j = 0; j < 16; j++) acc[j] = 0.f;
    __shared__ float avs[64][16];
    for (int nc = 0; nc < N_DIM / NSLICE; nc += 64) {
        __syncthreads();
        for (int i = threadIdx.x; i < 64 * 16; i += 256) {
            const int nn = i >> 4, bh = i & 15;
            avs[nn][bh] = g_av[((long)(bh >> 3) * N_DIM + nbeg + nc + nn) * HEADS + (bh & 7)];
        }
        __syncthreads();
        for (int nn = 0; nn < 64; nn++) {
            const float hv = H[(long)(nbeg + nc + nn) * E_DIM + e];
#pragma unroll
            for (int j = 0; j < 16; j++) acc[j] += hv * avs[nn][j];
        }
    }
#pragma unroll
    for (int j = 0; j < 16; j++)
        g_part[(((long)slice * BATCH + (j >> 3)) * E_DIM + e) * HEADS + (j & 7)] = acc[j];
}

__global__ __launch_bounds__(1024) void softmax_kernel() {
    const int bb = blockIdx.x >> 3, hh = blockIdx.x & 7;
    const int t = threadIdx.x;
    float v[E_DIM / 1024];
    float mx = -1e30f;
#pragma unroll
    for (int i = 0; i < E_DIM / 1024; i++) {
        const int e = i * 1024 + t;
        float s = 0.f;
        for (int sl = 0; sl < NSLICE; sl++)
            s += g_part[(((long)sl * BATCH + bb) * E_DIM + e) * HEADS + hh];
        v[i] = s; mx = fmaxf(mx, s);
    }
    __shared__ float red[1024];
    red[t] = mx; __syncthreads();
    for (int o = 512; o; o >>= 1) { if (t < o) red[t] = fmaxf(red[t], red[t + o]); __syncthreads(); }
    mx = red[0]; __syncthreads();
    float sum = 0.f;
#pragma unroll
    for (int i = 0; i < E_DIM / 1024; i++) { v[i] = __expf(v[i] - mx); sum += v[i]; }
    red[t] = sum; __syncthreads();
    for (int o = 512; o; o >>= 1) { if (t < o) red[t] += red[t + o]; __syncthreads(); }
    const float inv = 1.f / red[0];
#pragma unroll
    for (int i = 0; i < E_DIM / 1024; i++)
        g_aeT[((long)bb * HEADS + hh) * E_DIM + i * 1024 + t] = v[i] * inv;
}

// ---------------- launch: 2-stream fork-join (R13 resource envelope) ----------------
extern "C" void kernel_launch(void* const* d_in, const int* in_sizes, int n_in,
                              void* d_out, int out_size)
{
    const float* x = (const float*)d_in[0];
    const float* H = (const float*)d_in[1];
    const float* W = (const float*)d_in[2];
    const float* a = (const float*)d_in[3];
    float* out = (float*)d_out;

    __half *px16, *pW16T, *pHr16, *pHT16, *pWh16, *pWhT16, *pm2T16;
    float *paeT;
    cudaGetSymbolAddress((void**)&px16, g_x16);
    cudaGetSymbolAddress((void**)&pW16T, g_W16T);
    cudaGetSymbolAddress((void**)&pHr16, g_Hr16);
    cudaGetSymbolAddress((void**)&pHT16, g_HT16);
    cudaGetSymbolAddress((void**)&pWh16, g_Wh16);
    cudaGetSymbolAddress((void**)&pWhT16, g_WhT16);
    cudaGetSymbolAddress((void**)&pm2T16, g_m2T16);
    cudaGetSymbolAddress((void**)&paeT, g_aeT);

    cudaFuncSetAttribute(hgemm<0>, cudaFuncAttributeMaxDynamicSharedMemorySize, SMEM_SZ);
    cudaFuncSetAttribute(hgemm<2>, cudaFuncAttributeMaxDynamicSharedMemorySize, SMEM_SZ);
    cudaFuncSetAttribute(hgemm<3>, cudaFuncAttributeMaxDynamicSharedMemorySize, SMEM_SZ);

    // ONE side stream + 5 events (R13's proven teardown-safe envelope; created
    // per call, not destroyed — destroying capture-participating resources
    // mid-capture is UB)
    cudaStream_t s2;
    cudaStreamCreate(&s2);
    cudaEvent_t evFork, evG0, evTr, evSM, evJoin;
    cudaEventCreateWithFlags(&evFork, cudaEventDisableTiming);
    cudaEventCreateWithFlags(&evG0, cudaEventDisableTiming);
    cudaEventCreateWithFlags(&evTr, cudaEventDisableTiming);
    cudaEventCreateWithFlags(&evSM, cudaEventDisableTiming);
    cudaEventCreateWithFlags(&evJoin, cudaEventDisableTiming);

    // fork
    cudaEventRecord(evFork, 0);
    cudaStreamWaitEvent(s2, evFork, 0);

    // s2: prep_H (independent, DRAM-heavy)
    prep_H<<<dim3(E_DIM / 32, N_DIM / 32), 256, 0, s2>>>(H);

    // s0: pack x, transpose W, GEMM1 (+fused av)
    prep_pack<<<BATCH * N_DIM * FIN / 8 / 256, 256>>>(x, px16);
    prep_WT<<<dim3(HD / 32, FIN / 32), 256>>>(W);
    hgemm<0><<<dim3(HD / 128, (BATCH * N_DIM) / 128, 1), 128, SMEM_SZ>>>(
        px16, pW16T, pWh16, FIN, FIN, FIN, HD, a);
    cudaEventRecord(evG0, 0);

    // s2: trWh then batch-1 G5 (unscaled) — concurrent with s0's logits/softmax
    // (DRAM-bound logits co-runs with compute-bound G5)
    cudaStreamWaitEvent(s2, evG0, 0);
    trWh<<<dim3(HD / 32, BATCH * N_DIM / 32), 256, 0, s2>>>();
    cudaEventRecord(evTr, s2);
    hgemm<3><<<dim3(E_DIM / 128, HD / 128, 1), 128, SMEM_SZ, s2>>>(
        pWhT16 + (long)HD * N_DIM, pHT16, pm2T16 + (long)HD * E_DIM,
        N_DIM, N_DIM, N_DIM, E_DIM, nullptr);

    // s0: logits + softmax (after G1; concurrent with s2's trWh + G5 b1)
    logits_kernel<<<dim3(E_DIM / 256, NSLICE), 256>>>(H);
    softmax_kernel<<<BATCH * HEADS, 1024>>>();
    cudaEventRecord(evSM, 0);

    // s2: finish batch-1 (scale needs softmax; Hr16 from prep_H — same stream)
    cudaStreamWaitEvent(s2, evSM, 0);
    scale_m2<<<(HD * E_DIM / 8) / 256, 256, 0, s2>>>(
        pm2T16 + (long)HD * E_DIM, paeT + (long)HEADS * E_DIM);
    hgemm<2><<<dim3(HD / 128, N_DIM / 128, 1), 128, SMEM_SZ, s2>>>(
        pHr16, pm2T16 + (long)HD * E_DIM, out + (long)N_DIM * HD,
        E_DIM, E_DIM, E_DIM, HD, nullptr);

    // s0: batch-0 chain (needs trWh + prep_H from s2, both covered by evTr)
    cudaStreamWaitEvent(0, evTr, 0);
    hgemm<3><<<dim3(E_DIM / 128, HD / 128, 1), 128, SMEM_SZ>>>(
        pWhT16, pHT16, pm2T16, N_DIM, N_DIM, N_DIM, E_DIM, nullptr);
    scale_m2<<<(HD * E_DIM / 8) / 256, 256>>>(pm2T16, paeT);
    hgemm<2><<<dim3(HD / 128, N_DIM / 128, 1), 128, SMEM_SZ>>>(
        pHr16, pm2T16, out, E_DIM, E_DIM, E_DIM, HD, nullptr);

    // join
    cudaEventRecord(evJoin, s2);
    cudaStreamWaitEvent(0, evJoin, 0);
}

// round 17
// speedup vs baseline: 1.1703x; 1.0652x over previous
#include <cuda_runtime.h>
#include <cuda_fp16.h>
#include <cstdint>

#define E_DIM 4096
#define N_DIM 8192
#define FIN   256
#define HEADS 8
#define DOUT  64
#define HD    512
#define BATCH 2
#define LRELU_ALPHA 0.2f
#define NSLICE 16

// ---------------- scratch (fp16 operands, natural K-major layout) ----------------
__device__ __align__(16) __half g_x16[BATCH * N_DIM * FIN];
__device__ __align__(16) __half g_W16T[HD * FIN];
__device__ __align__(16) __half g_Hr16[N_DIM * E_DIM];       // (n, e)
__device__ __align__(16) __half g_HT16[E_DIM * N_DIM];       // (e, n)
__device__ __align__(16) __half g_WhT16[BATCH * HD * N_DIM]; // (b*hd, n) - written by G1 epilogue
__device__ __align__(16) __half g_m2T16[BATCH * HD * E_DIM]; // (b*hd, e); unscaled then ae-scaled
__device__ float g_av[BATCH * N_DIM * HEADS];
__device__ float g_part[NSLICE * BATCH * E_DIM * HEADS];
__device__ float g_aeT[BATCH * HEADS * E_DIM];

__device__ __forceinline__ uint32_t smem_u32(const void* p) {
    uint32_t a;
    asm("{ .reg .u64 t; cvta.to.shared.u64 t, %1; cvt.u32.u64 %0, t; }" : "=r"(a) : "l"(p));
    return a;
}
__device__ __forceinline__ void cpa16(uint32_t dst, const void* src) {
    asm volatile("cp.async.cg.shared.global [%0], [%1], 16;" :: "r"(dst), "l"(src));
}
#define LDSM4(r0, r1, r2, r3, addr) \
    asm volatile("ldmatrix.sync.aligned.m8n8.x4.shared.b16 {%0,%1,%2,%3}, [%4];" \
        : "=r"(r0), "=r"(r1), "=r"(r2), "=r"(r3) : "r"(addr))

#define MMA_F16(c, a, b) \
    asm volatile("mma.sync.aligned.m16n8k16.row.col.f32.f16.f16.f32 " \
        "{%0,%1,%2,%3}, {%4,%5,%6,%7}, {%8,%9}, {%0,%1,%2,%3};" \
        : "+f"((c)[0]), "+f"((c)[1]), "+f"((c)[2]), "+f"((c)[3]) \
        : "r"((a)[0]), "r"((a)[1]), "r"((a)[2]), "r"((a)[3]), \
          "r"((b)[0]), "r"((b)[1]))

#define STG_BYTES 32768               // A 16KB + B 16KB (128 rows x 128B = 64 fp16)
#define STAGES 3
#define SMEM_SZ (STAGES * STG_BYTES)  // 96 KB

// ---------------- fp16 mma GEMM: CTA 128x128, 4 warps (64x64), K-step 64 ----------------
// A: (M x K) fp16 K-major.  B: (N x K) fp16 K-major.  smem swizzle: group j ^ (row & 7).
// EPI 0: transposed fp16 store into WhT16 (smem-staged) + fused av (aeT = a_vertices)
// EPI 2: fp32 store into out with batch split at col 512 (merged G6)
// EPI 3: fp16 plain store (unscaled m2T, merged G5)
template<int EPI>
__global__ void __launch_bounds__(128, 2) hgemm(
    const __half* __restrict__ A, const __half* __restrict__ B, void* __restrict__ Cv,
    int K, int lda, int ldb, int ldc, const float* __restrict__ aeT)
{
    extern __shared__ char smem[];
    const uint32_t sb = smem_u32(smem);
    const int tid = threadIdx.x, lane = tid & 31, wid = tid >> 5;
    const int wm = wid >> 1, wn = wid & 1;
    const int m0 = blockIdx.y * 128, n0 = blockIdx.x * 128;

    const __half* Ag = A + (long)m0 * lda;
    const __half* Bg = B + (long)n0 * ldb;

    auto load_stage = [&](int st, int k0) {
        const uint32_t sA = sb + st * STG_BYTES;
#pragma unroll
        for (int i = 0; i < 8; i++) {
            const int id = tid + i * 128;
            const int r = id >> 3, j = id & 7;
            cpa16(sA + r * 128 + ((j ^ (r & 7)) << 4), Ag + (long)r * lda + k0 + j * 8);
        }
        const uint32_t sB = sA + 16384;
#pragma unroll
        for (int i = 0; i < 8; i++) {
            const int id = tid + i * 128;
            const int r = id >> 3, j = id & 7;
            cpa16(sB + r * 128 + ((j ^ (r & 7)) << 4), Bg + (long)r * ldb + k0 + j * 8);
        }
    };

    float acc[4][8][4];
#pragma unroll
    for (int mt = 0; mt < 4; mt++)
#pragma unroll
        for (int nt = 0; nt < 8; nt++)
#pragma unroll
            for (int s = 0; s < 4; s++) acc[mt][nt][s] = 0.f;

    // ldmatrix per-lane geometry
    const int l7 = lane & 7, sub = lane >> 3;
    const int rowAl = (sub & 1) * 8 + l7;
    const int kgA = sub >> 1;
    const int rowBl = (sub >> 1) * 8 + l7;
    const int kgB = sub & 1;

    const int T = K / 64;
    load_stage(0, 0);
    asm volatile("cp.async.commit_group;" ::: "memory");
    load_stage(1, 64);
    asm volatile("cp.async.commit_group;" ::: "memory");

    for (int t = 0; t < T; t++) {
        asm volatile("cp.async.wait_group 1;" ::: "memory");
        __syncthreads();
        const int u = t + 2;
        if (u < T) load_stage(u % 3, u * 64);
        asm volatile("cp.async.commit_group;" ::: "memory");

        const uint32_t Ab = sb + (t % 3) * STG_BYTES;
        const uint32_t Bb = Ab + 16384;
        const uint32_t aRow = Ab + (wm * 64 + rowAl) * 128;
        const uint32_t bRow = Bb + (wn * 64 + rowBl) * 128;
#pragma unroll
        for (int kk = 0; kk < 4; kk++) {          // each kk = K=16
            const uint32_t gA = (uint32_t)((((kk << 1) | kgA) ^ l7) << 4);
            const uint32_t gB = (uint32_t)((((kk << 1) | kgB) ^ l7) << 4);
            uint32_t af[4][4], bf[8][2];
#pragma unroll
            for (int mt = 0; mt < 4; mt++)
                LDSM4(af[mt][0], af[mt][1], af[mt][2], af[mt][3],
                      aRow + mt * 16 * 128 + gA);
#pragma unroll
            for (int np = 0; np < 4; np++)
                LDSM4(bf[2 * np][0], bf[2 * np][1], bf[2 * np + 1][0], bf[2 * np + 1][1],
                      bRow + np * 16 * 128 + gB);
#pragma unroll
            for (int mt = 0; mt < 4; mt++)
#pragma unroll
                for (int nt = 0; nt < 8; nt++)
                    MMA_F16(acc[mt][nt], af[mt], bf[nt]);
        }
    }

    // ---------------- epilogue ----------------
    const int r4 = lane >> 2, cl = lane & 3;
    if (EPI == 0) {
        // fused av + smem-staged transpose -> WhT16[(b*HD + col)*N_DIM + n]
        const int b = m0 >> 13;                   // m0 flat over B*N, N_DIM = 8192
        const int nloc = m0 & (N_DIM - 1);
        const int head = (n0 >> 6) + wn;
        float aw0[8], aw1[8];
#pragma unroll
        for (int nt = 0; nt < 8; nt++) {
            aw0[nt] = aeT[nt * 8 + 2 * cl];
            aw1[nt] = aeT[nt * 8 + 2 * cl + 1];
        }
        __syncthreads();                          // mainloop smem reads all done
        __half* sm = (__half*)smem;               // staged as [128 rows][130 cols]
#pragma unroll
        for (int mt = 0; mt < 4; mt++) {
            const int rl = wm * 64 + mt * 16 + r4;
            const int row = m0 + rl;
            float s0 = 0.f, s1 = 0.f;
#pragma unroll
            for (int nt = 0; nt < 8; nt++) {
                const int colL = wn * 64 + nt * 8 + 2 * cl;
                const __half h0 = __float2half_rn(acc[mt][nt][0]);
                const __half h1 = __float2half_rn(acc[mt][nt][1]);
                const __half h2 = __float2half_rn(acc[mt][nt][2]);
                const __half h3 = __float2half_rn(acc[mt][nt][3]);
                *(__half2*)&sm[rl * 130 + colL] = __halves2half2(h0, h1);
                *(__half2*)&sm[(rl + 8) * 130 + colL] = __halves2half2(h2, h3);
                s0 += __half2float(h0) * aw0[nt] + __half2float(h1) * aw1[nt];
                s1 += __half2float(h2) * aw0[nt] + __half2float(h3) * aw1[nt];
            }
            s0 += __shfl_xor_sync(0xffffffffu, s0, 1);
            s0 += __shfl_xor_sync(0xffffffffu, s0, 2);
            s1 += __shfl_xor_sync(0xffffffffu, s1, 1);
            s1 += __shfl_xor_sync(0xffffffffu, s1, 2);
            if (cl == 0) {
                g_av[(long)row * HEADS + head] =
                    fmaxf(s0, 0.f) + LRELU_ALPHA * fminf(s0, 0.f);
                g_av[(long)(row + 8) * HEADS + head] =
                    fmaxf(s1, 0.f) + LRELU_ALPHA * fminf(s1, 0.f);
            }
        }
        __syncthreads();
        // write-out: 2048 uint4 (128 cols x 16 segs of 8 n), coalesced
#pragma unroll
        for (int it = 0; it < 16; it++) {
            const int q = tid + it * 128;
            const int col = q >> 4, nseg = q & 15;
            __align__(16) __half hb[8];
#pragma unroll
            for (int j = 0; j < 8; j++)
                hb[j] = sm[(nseg * 8 + j) * 130 + col];
            *(uint4*)&g_WhT16[((long)b * HD + n0 + col) * N_DIM + nloc + nseg * 8] =
                *(const uint4*)hb;
        }
    } else if (EPI == 3) {
        __half* Cb = (__half*)Cv;
#pragma unroll
        for (int mt = 0; mt < 4; mt++) {
            const int row = m0 + wm * 64 + mt * 16 + r4;
#pragma unroll
            for (int nt = 0; nt < 8; nt++) {
                const int col = n0 + wn * 64 + nt * 8 + 2 * cl;
                *(__half2*)&Cb[(long)row * ldc + col] = __halves2half2(
                    __float2half_rn(acc[mt][nt][0]), __float2half_rn(acc[mt][nt][1]));
                *(__half2*)&Cb[(long)(row + 8) * ldc + col] = __halves2half2(
                    __float2half_rn(acc[mt][nt][2]), __float2half_rn(acc[mt][nt][3]));
            }
        }
    } else {
        // EPI 2: merged-G6 store. col in [0,1024); batch = n0>>9 (tiles never straddle 512)
        float* Cb = (float*)Cv + (long)(n0 >> 9) * N_DIM * HD;
        const int ncol0 = n0 & 511;
#pragma unroll
        for (int mt = 0; mt < 4; mt++) {
            const int row = m0 + wm * 64 + mt * 16 + r4;
#pragma unroll
            for (int nt = 0; nt < 8; nt++) {
                const int col = ncol0 + wn * 64 + nt * 8 + 2 * cl;
                float2 o0 = {acc[mt][nt][0], acc[mt][nt][1]};
                float2 o1 = {acc[mt][nt][2], acc[mt][nt][3]};
                *(float2*)&Cb[(long)row * HD + col] = o0;
                *(float2*)&Cb[(long)(row + 8) * HD + col] = o1;
            }
        }
    }
}

// ---------------- merged ae scaling: m2T[b*HD+hd, e] *= aeT[b, hd/64, e] -------------
__global__ __launch_bounds__(256) void scale_m2() {
    const int idx = blockIdx.x * 256 + threadIdx.x;        // uint4 id = 8 halfs
    const int perRow = E_DIM / 8;                          // 512 uint4 per row
    const int hd = idx / perRow, e0 = (idx % perRow) * 8;  // hd in [0, 1024)
    const float* ae = g_aeT + (long)(hd >> 6) * E_DIM + e0; // (b*8 + head) rows
    uint4 v = ((uint4*)g_m2T16)[idx];
    __half2* h2 = (__half2*)&v;
#pragma unroll
    for (int i = 0; i < 4; i++) {
        float2 f = __half22float2(h2[i]);
        f.x *= ae[2 * i]; f.y *= ae[2 * i + 1];
        h2[i] = __float22half2_rn(f);
    }
    ((uint4*)g_m2T16)[idx] = v;
}

// ---------------- prep kernels ----------------
__global__ __launch_bounds__(256) void prep_pack(const float* __restrict__ src,
                                                 __half* __restrict__ dst) {
    const long i = (long)blockIdx.x * 256 + threadIdx.x;
    float4 v0 = ((const float4*)src)[i * 2];
    float4 v1 = ((const float4*)src)[i * 2 + 1];
    __align__(16) __half h[8];
    h[0] = __float2half_rn(v0.x); h[1] = __float2half_rn(v0.y);
    h[2] = __float2half_rn(v0.z); h[3] = __float2half_rn(v0.w);
    h[4] = __float2half_rn(v1.x); h[5] = __float2half_rn(v1.y);
    h[6] = __float2half_rn(v1.z); h[7] = __float2half_rn(v1.w);
    ((uint4*)dst)[i] = *(const uint4*)h;
}
__global__ __launch_bounds__(256) void prep_WT(const float* __restrict__ W) {
    __shared__ float ts[32][33];
    const int o0 = blockIdx.x * 32, i0 = blockIdx.y * 32;
    const int tx = threadIdx.x & 31, ty = threadIdx.x >> 5;
#pragma unroll
    for (int r8 = 0; r8 < 4; r8++) {
        const int il = ty + r8 * 8;
        ts[tx][il] = W[(long)(i0 + il) * HD + o0 + tx];
    }
    __syncthreads();
#pragma unroll
    for (int r8 = 0; r8 < 4; r8++) {
        const int ol = ty + r8 * 8;
        g_W16T[(long)(o0 + ol) * FIN + i0 + tx] = __float2half_rn(ts[ol][tx]);
    }
}
__global__ __launch_bounds__(256) void prep_H(const float* __restrict__ H) {
    __shared__ __half ts[32][34];
    const int e0 = blockIdx.x * 32, n0 = blockIdx.y * 32;
    const int tx = threadIdx.x & 31, ty = threadIdx.x >> 5;
#pragma unroll
    for (int r8 = 0; r8 < 4; r8++) {
        const int nl = ty + r8 * 8;
        const __half h = __float2half_rn(H[(long)(n0 + nl) * E_DIM + e0 + tx]);
        g_Hr16[(long)(n0 + nl) * E_DIM + e0 + tx] = h;
        ts[tx][nl] = h;
    }
    __syncthreads();
#pragma unroll
    for (int r8 = 0; r8 < 4; r8++) {
        const int el = ty + r8 * 8;
        g_HT16[(long)(e0 + el) * N_DIM + n0 + tx] = ts[el][tx];
    }
}

// ---------------- logits / softmax (exact fp32) ----------------
__global__ __launch_bounds__(256) void logits_kernel(const float* __restrict__ H) {
    const int e = blockIdx.x * 256 + threadIdx.x;
    const int slice = blockIdx.y;
    const int nbeg = slice * (N_DIM / NSLICE);
    float acc[16];
#pragma unroll
    for (int j = 0; j < 16; j++) acc[j] = 0.f;
    __shared__ float avs[64][16];
    for (int nc = 0; nc < N_DIM / NSLICE; nc += 64) {
        __syncthreads();
        for (int i = threadIdx.x; i < 64 * 16; i += 256) {
            const int nn = i >> 4, bh = i & 15;
            avs[nn][bh] = g_av[((long)(bh >> 3) * N_DIM + nbeg + nc + nn) * HEADS + (bh & 7)];
        }
        __syncthreads();
        for (int nn = 0; nn < 64; nn++) {
            const float hv = H[(long)(nbeg + nc + nn) * E_DIM + e];
#pragma unroll
            for (int j = 0; j < 16; j++) acc[j] += hv * avs[nn][j];
        }
    }
#pragma unroll
    for (int j = 0; j < 16; j++)
        g_part[(((long)slice * BATCH + (j >> 3)) * E_DIM + e) * HEADS + (j & 7)] = acc[j];
}

__global__ __launch_bounds__(1024) void softmax_kernel() {
    const int bb = blockIdx.x >> 3, hh = blockIdx.x & 7;
    const int t = threadIdx.x;
    float v[E_DIM / 1024];
    float mx = -1e30f;
#pragma unroll
    for (int i = 0; i < E_DIM / 1024; i++) {
        const int e = i * 1024 + t;
        float s = 0.f;
        for (int sl = 0; sl < NSLICE; sl++)
            s += g_part[(((long)sl * BATCH + bb) * E_DIM + e) * HEADS + hh];
        v[i] = s; mx = fmaxf(mx, s);
    }
    __shared__ float red[1024];
    red[t] = mx; __syncthreads();
    for (int o = 512; o; o >>= 1) { if (t < o) red[t] = fmaxf(red[t], red[t + o]); __syncthreads(); }
    mx = red[0]; __syncthreads();
    float sum = 0.f;
#pragma unroll
    for (int i = 0; i < E_DIM / 1024; i++) { v[i] = __expf(v[i] - mx); sum += v[i]; }
    red[t] = sum; __syncthreads();
    for (int o = 512; o; o >>= 1) { if (t < o) red[t] += red[t + o]; __syncthreads(); }
    const float inv = 1.f / red[0];
#pragma unroll
    for (int i = 0; i < E_DIM / 1024; i++)
        g_aeT[((long)bb * HEADS + hh) * E_DIM + i * 1024 + t] = v[i] * inv;
}

// ---------------- launch: 2-stream fork-join, merged batch GEMMs ----------------
extern "C" void kernel_launch(void* const* d_in, const int* in_sizes, int n_in,
                              void* d_out, int out_size)
{
    const float* x = (const float*)d_in[0];
    const float* H = (const float*)d_in[1];
    const float* W = (const float*)d_in[2];
    const float* a = (const float*)d_in[3];
    float* out = (float*)d_out;

    __half *px16, *pW16T, *pHr16, *pHT16, *pWhT16, *pm2T16;
    cudaGetSymbolAddress((void**)&px16, g_x16);
    cudaGetSymbolAddress((void**)&pW16T, g_W16T);
    cudaGetSymbolAddress((void**)&pHr16, g_Hr16);
    cudaGetSymbolAddress((void**)&pHT16, g_HT16);
    cudaGetSymbolAddress((void**)&pWhT16, g_WhT16);
    cudaGetSymbolAddress((void**)&pm2T16, g_m2T16);

    cudaFuncSetAttribute(hgemm<0>, cudaFuncAttributeMaxDynamicSharedMemorySize, SMEM_SZ);
    cudaFuncSetAttribute(hgemm<2>, cudaFuncAttributeMaxDynamicSharedMemorySize, SMEM_SZ);
    cudaFuncSetAttribute(hgemm<3>, cudaFuncAttributeMaxDynamicSharedMemorySize, SMEM_SZ);

    // ONE side stream + 4 events (within R13's proven teardown-safe envelope;
    // created per call, not destroyed — destroying capture-participating
    // resources mid-capture is UB)
    cudaStream_t s2;
    cudaStreamCreate(&s2);
    cudaEvent_t evFork, evH, evG0, evSM;
    cudaEventCreateWithFlags(&evFork, cudaEventDisableTiming);
    cudaEventCreateWithFlags(&evH, cudaEventDisableTiming);
    cudaEventCreateWithFlags(&evG0, cudaEventDisableTiming);
    cudaEventCreateWithFlags(&evSM, cudaEventDisableTiming);

    // fork
    cudaEventRecord(evFork, 0);
    cudaStreamWaitEvent(s2, evFork, 0);

    // s2: prep_H (independent, DRAM-heavy)
    prep_H<<<dim3(E_DIM / 32, N_DIM / 32), 256, 0, s2>>>(H);
    cudaEventRecord(evH, s2);

    // s0: pack x, transpose W, G1 (+fused av, direct WhT16 store)
    prep_pack<<<BATCH * N_DIM * FIN / 8 / 256, 256>>>(x, px16);
    prep_WT<<<dim3(HD / 32, FIN / 32), 256>>>(W);
    hgemm<0><<<dim3(HD / 128, (BATCH * N_DIM) / 128, 1), 128, SMEM_SZ>>>(
        px16, pW16T, nullptr, FIN, FIN, FIN, 0, a);
    cudaEventRecord(evG0, 0);

    // s2: logits + softmax (after G1; concurrent with s0's merged G5)
    cudaStreamWaitEvent(s2, evG0, 0);
    logits_kernel<<<dim3(E_DIM / 256, NSLICE), 256, 0, s2>>>(H);
    softmax_kernel<<<BATCH * HEADS, 1024, 0, s2>>>();
    cudaEventRecord(evSM, s2);

    // s0: merged G5 (M = BATCH*HD = 1024, N = E, K = N_DIM) -> unscaled m2T
    cudaStreamWaitEvent(0, evH, 0);
    hgemm<3><<<dim3(E_DIM / 128, BATCH * HD / 128, 1), 128, SMEM_SZ>>>(
        pWhT16, pHT16, pm2T16, N_DIM, N_DIM, N_DIM, E_DIM, nullptr);

    // s0: merged scale (needs softmax) then merged G6
    cudaStreamWaitEvent(0, evSM, 0);
    scale_m2<<<(BATCH * HD * E_DIM / 8) / 256, 256>>>();
    hgemm<2><<<dim3(BATCH * HD / 128, N_DIM / 128, 1), 128, SMEM_SZ>>>(
        pHr16, pm2T16, out, E_DIM, E_DIM, E_DIM, HD, nullptr);
}